// round 7
// baseline (speedup 1.0000x reference)
#include <cuda_runtime.h>
#include <cstdint>

#define BN 512
#define NSTEPS 100

// ---------------- persistent device state (allocation-free scratch) ----------------
__device__ float g_m1 [BN * 20 * 784];     // conv1 membrane
__device__ float g_m1s[BN * 20 * 196];     // pool1 membrane
__device__ float g_op1[BN * 20 * 196];     // pool1 output spikes (binary)
__device__ float g_m2 [BN * 50 * 196];     // conv2 membrane
__device__ float g_m2s[BN * 50 * 49];      // pool2 membrane
__device__ float g_op2[BN * 2450];         // pool2 output spikes, layout (b, co*49+q)
__device__ float g_mf0[BN * 200];          // fc0 membrane
__device__ float g_tf0[BN * 200];          // fc0 total spike count (ONLY output that matters)
__device__ float g_yp [5 * BN * 200];      // fc0 K-split partials (order proven output-neutral)

// ---------------- Threefry-2x32, 20 rounds (matches JAX exactly) ----------------
__host__ __device__ __forceinline__ void tf2x32(uint32_t k0, uint32_t k1,
                                                uint32_t x0, uint32_t x1,
                                                uint32_t& o0, uint32_t& o1) {
    uint32_t k2 = k0 ^ k1 ^ 0x1BD11BDAu;
    x0 += k0; x1 += k1;
#define TFR(r) { x0 += x1; x1 = (x1 << (r)) | (x1 >> (32 - (r))); x1 ^= x0; }
    TFR(13) TFR(15) TFR(26) TFR(6)   x0 += k1; x1 += k2 + 1u;
    TFR(17) TFR(29) TFR(16) TFR(24)  x0 += k2; x1 += k0 + 2u;
    TFR(13) TFR(15) TFR(26) TFR(6)   x0 += k0; x1 += k1 + 3u;
    TFR(17) TFR(29) TFR(16) TFR(24)  x0 += k1; x1 += k2 + 4u;
    TFR(13) TFR(15) TFR(26) TFR(6)   x0 += k2; x1 += k0 + 5u;
#undef TFR
    o0 = x0; o1 = x1;
}

// ---------------- conv1 (RNG fused) + fire(1.0) + avgpool2 + fire(0.75) ----------------
// grid (b, 4 channel-groups of 5). 224 threads; 196 compute one pooled position each.
// RNG recomputed per block (cheap); chains per output unchanged ((ky,kx) sequential).
__global__ __launch_bounds__(224) void k_conv1(const float* __restrict__ in,
                                               const float* __restrict__ w1,
                                               uint32_t k0, uint32_t k1) {
    int b  = blockIdx.x;
    int c5 = blockIdx.y * 5;
    __shared__ float sin_[32][32];   // padded 28x28 (+2 halo)
    __shared__ float sw[125];        // 5 x 25 weights
    int t = threadIdx.x;
    for (int i = t; i < 1024; i += blockDim.x) ((float*)sin_)[i] = 0.f;
    for (int i = t; i < 125;  i += blockDim.x) sw[i] = w1[c5 * 25 + i];
    __syncthreads();
    for (int i = t; i < 784; i += blockDim.x) {
        uint32_t o0, o1;
        tf2x32(k0, k1, 0u, (uint32_t)(b * 784 + i), o0, o1);
        uint32_t bits = o0 ^ o1;
        float u = __uint_as_float((bits >> 9) | 0x3f800000u) - 1.0f;
        float v = in[b * 784 + i];
        float sgn = (v > 0.f) ? 1.f : ((v < 0.f) ? -1.f : 0.f);
        sin_[2 + i / 28][2 + i % 28] = (fabsf(v) * 0.5f > u) ? sgn : 0.f;
    }
    __syncthreads();

    if (t < 196) {
        int py = t / 14, px = t % 14;
        int r0 = 2 * py, c0 = 2 * px;
        float p[6][6];
#pragma unroll
        for (int r = 0; r < 6; r++)
#pragma unroll
            for (int c = 0; c < 6; c++) p[r][c] = sin_[r0 + r][c0 + c];

#pragma unroll 1
        for (int cl = 0; cl < 5; cl++) {
            int ch = c5 + cl;
            const float* w = &sw[cl * 25];
            float a00 = 0.f, a01 = 0.f, a10 = 0.f, a11 = 0.f;
#pragma unroll
            for (int ky = 0; ky < 5; ky++)
#pragma unroll
                for (int kx = 0; kx < 5; kx++) {
                    float wv = w[ky * 5 + kx];
                    a00 = __fmaf_rn(p[ky][kx],         wv, a00);
                    a01 = __fmaf_rn(p[ky][kx + 1],     wv, a01);
                    a10 = __fmaf_rn(p[ky + 1][kx],     wv, a10);
                    a11 = __fmaf_rn(p[ky + 1][kx + 1], wv, a11);
                }
            size_t mb = (size_t)(b * 20 + ch) * 784;
            int i00 = r0 * 28 + c0;
            float m00 = g_m1[mb + i00]      + a00;
            float m01 = g_m1[mb + i00 + 1]  + a01;
            float m10 = g_m1[mb + i00 + 28] + a10;
            float m11 = g_m1[mb + i00 + 29] + a11;
            float f00 = (m00 > 1.f) ? 1.f : 0.f; g_m1[mb + i00]      = (m00 > 1.f) ? 0.f : m00;
            float f01 = (m01 > 1.f) ? 1.f : 0.f; g_m1[mb + i00 + 1]  = (m01 > 1.f) ? 0.f : m01;
            float f10 = (m10 > 1.f) ? 1.f : 0.f; g_m1[mb + i00 + 28] = (m10 > 1.f) ? 0.f : m10;
            float f11 = (m11 > 1.f) ? 1.f : 0.f; g_m1[mb + i00 + 29] = (m11 > 1.f) ? 0.f : m11;
            int pi = (b * 20 + ch) * 196 + t;
            float ms = g_m1s[pi] + 0.25f * (f00 + f01 + f10 + f11);
            float op = (ms > 0.75f) ? 1.f : 0.f;
            g_m1s[pi] = (ms > 0.75f) ? 0.f : ms;
            g_op1[pi] = op;
        }
    }
}

// ---------------- conv2: (ky,kx,ci) chains unchanged; spikes loaded as float2 ci-pairs ----------------
// grid (b, 2): 25 output channels per block. 256 threads = 5 cogs x 49 positions.
// Spike smem layout addr = r*396 + c*22 + ci (even -> 8B aligned float2 loads).
#define SP_RS 396
#define SP_CS 22
#define SP_SZ 7136
#define C2_SMEM ((SP_SZ + 12500) * 4)
__global__ __launch_bounds__(256) void k_conv2(const float* __restrict__ w2) {
    extern __shared__ float dyn[];
    float* sp  = dyn;           // 18*396 = 7128 floats (zero-padded halo)
    float* swt = dyn + SP_SZ;   // 25*500 floats, [ch][kk*20+ci]
    int b  = blockIdx.x;
    int cb = blockIdx.y * 25;
    int t = threadIdx.x;
    for (int i = t; i < SP_SZ; i += 256) sp[i] = 0.f;
    for (int i = t; i < 12500; i += 256) {
        int ch = i / 500, rem = i % 500, kk = rem / 20, ci = rem % 20;
        swt[i] = w2[(cb + ch) * 500 + ci * 25 + kk];
    }
    __syncthreads();
    for (int i = t; i < 3920; i += 256) {
        int ci = i / 196, pos = i % 196, rr = pos / 14, cc = pos % 14;
        sp[(rr + 2) * SP_RS + (cc + 2) * SP_CS + ci] = g_op1[(b * 20 + ci) * 196 + pos];
    }
    __syncthreads();

    if (t < 245) {
        int cog = t / 49, q = t % 49;
        int py = q / 7, px = q % 7;
        int r0 = 2 * py, c0 = 2 * px;
        float acc[5][4] = {};
        const float* wb = &swt[cog * 5 * 500];
        int sbase = r0 * SP_RS + c0 * SP_CS;
#pragma unroll 1
        for (int ky = 0; ky < 5; ky++) {
#pragma unroll 1
            for (int kx = 0; kx < 5; kx++) {
                const float* s00 = &sp[sbase + ky * SP_RS + kx * SP_CS];
                const float* s10 = s00 + SP_RS;
                const float* wk  = &wb[(ky * 5 + kx) * 20];
#pragma unroll
                for (int ci = 0; ci < 20; ci += 2) {
                    float2 w0 = *(const float2*)&wk[0 * 500 + ci];
                    float2 w1 = *(const float2*)&wk[1 * 500 + ci];
                    float2 w2v = *(const float2*)&wk[2 * 500 + ci];
                    float2 w3 = *(const float2*)&wk[3 * 500 + ci];
                    float2 w4 = *(const float2*)&wk[4 * 500 + ci];
                    float2 q0 = *(const float2*)&s00[ci];           // pos00 (ci, ci+1)
                    float2 q1 = *(const float2*)&s00[SP_CS + ci];   // pos01
                    float2 q2 = *(const float2*)&s10[ci];           // pos10
                    float2 q3 = *(const float2*)&s10[SP_CS + ci];   // pos11
                    // per accumulator: ci first, then ci+1 — ascending-ci chain preserved
                    acc[0][0] = __fmaf_rn(q0.x, w0.x, acc[0][0]);
                    acc[0][1] = __fmaf_rn(q1.x, w0.x, acc[0][1]);
                    acc[0][2] = __fmaf_rn(q2.x, w0.x, acc[0][2]);
                    acc[0][3] = __fmaf_rn(q3.x, w0.x, acc[0][3]);
                    acc[1][0] = __fmaf_rn(q0.x, w1.x, acc[1][0]);
                    acc[1][1] = __fmaf_rn(q1.x, w1.x, acc[1][1]);
                    acc[1][2] = __fmaf_rn(q2.x, w1.x, acc[1][2]);
                    acc[1][3] = __fmaf_rn(q3.x, w1.x, acc[1][3]);
                    acc[2][0] = __fmaf_rn(q0.x, w2v.x, acc[2][0]);
                    acc[2][1] = __fmaf_rn(q1.x, w2v.x, acc[2][1]);
                    acc[2][2] = __fmaf_rn(q2.x, w2v.x, acc[2][2]);
                    acc[2][3] = __fmaf_rn(q3.x, w2v.x, acc[2][3]);
                    acc[3][0] = __fmaf_rn(q0.x, w3.x, acc[3][0]);
                    acc[3][1] = __fmaf_rn(q1.x, w3.x, acc[3][1]);
                    acc[3][2] = __fmaf_rn(q2.x, w3.x, acc[3][2]);
                    acc[3][3] = __fmaf_rn(q3.x, w3.x, acc[3][3]);
                    acc[4][0] = __fmaf_rn(q0.x, w4.x, acc[4][0]);
                    acc[4][1] = __fmaf_rn(q1.x, w4.x, acc[4][1]);
                    acc[4][2] = __fmaf_rn(q2.x, w4.x, acc[4][2]);
                    acc[4][3] = __fmaf_rn(q3.x, w4.x, acc[4][3]);
                    acc[0][0] = __fmaf_rn(q0.y, w0.y, acc[0][0]);
                    acc[0][1] = __fmaf_rn(q1.y, w0.y, acc[0][1]);
                    acc[0][2] = __fmaf_rn(q2.y, w0.y, acc[0][2]);
                    acc[0][3] = __fmaf_rn(q3.y, w0.y, acc[0][3]);
                    acc[1][0] = __fmaf_rn(q0.y, w1.y, acc[1][0]);
                    acc[1][1] = __fmaf_rn(q1.y, w1.y, acc[1][1]);
                    acc[1][2] = __fmaf_rn(q2.y, w1.y, acc[1][2]);
                    acc[1][3] = __fmaf_rn(q3.y, w1.y, acc[1][3]);
                    acc[2][0] = __fmaf_rn(q0.y, w2v.y, acc[2][0]);
                    acc[2][1] = __fmaf_rn(q1.y, w2v.y, acc[2][1]);
                    acc[2][2] = __fmaf_rn(q2.y, w2v.y, acc[2][2]);
                    acc[2][3] = __fmaf_rn(q3.y, w2v.y, acc[2][3]);
                    acc[3][0] = __fmaf_rn(q0.y, w3.y, acc[3][0]);
                    acc[3][1] = __fmaf_rn(q1.y, w3.y, acc[3][1]);
                    acc[3][2] = __fmaf_rn(q2.y, w3.y, acc[3][2]);
                    acc[3][3] = __fmaf_rn(q3.y, w3.y, acc[3][3]);
                    acc[4][0] = __fmaf_rn(q0.y, w4.y, acc[4][0]);
                    acc[4][1] = __fmaf_rn(q1.y, w4.y, acc[4][1]);
                    acc[4][2] = __fmaf_rn(q2.y, w4.y, acc[4][2]);
                    acc[4][3] = __fmaf_rn(q3.y, w4.y, acc[4][3]);
                }
            }
        }
#pragma unroll
        for (int u = 0; u < 5; u++) {
            int co = cb + cog * 5 + u;
            size_t mb = (size_t)(b * 50 + co) * 196;
            int i00 = r0 * 14 + c0;
            float m00 = g_m2[mb + i00]      + acc[u][0];
            float m01 = g_m2[mb + i00 + 1]  + acc[u][1];
            float m10 = g_m2[mb + i00 + 14] + acc[u][2];
            float m11 = g_m2[mb + i00 + 15] + acc[u][3];
            float f00 = (m00 > 1.f) ? 1.f : 0.f; g_m2[mb + i00]      = (m00 > 1.f) ? 0.f : m00;
            float f01 = (m01 > 1.f) ? 1.f : 0.f; g_m2[mb + i00 + 1]  = (m01 > 1.f) ? 0.f : m01;
            float f10 = (m10 > 1.f) ? 1.f : 0.f; g_m2[mb + i00 + 14] = (m10 > 1.f) ? 0.f : m10;
            float f11 = (m11 > 1.f) ? 1.f : 0.f; g_m2[mb + i00 + 15] = (m11 > 1.f) ? 0.f : m11;
            int pi = (b * 50 + co) * 49 + q;
            float ms = g_m2s[pi] + 0.25f * (f00 + f01 + f10 + f11);
            float op = (ms > 0.75f) ? 1.f : 0.f;
            g_m2s[pi] = (ms > 0.75f) ? 0.f : ms;
            g_op2[b * 2450 + co * 49 + q] = op;
        }
    }
}

// ---------------- fc0 GEMM split-K x5 (proven output-neutral), scalar ----------------
__global__ __launch_bounds__(128) void k_fc0(const float* __restrict__ wf0) {
    int mb = blockIdx.x * 32;
    int nb = blockIdx.y * 40;
    int kb = blockIdx.z * 490;
    __shared__ float si[32][36];
    __shared__ float swt[40][36];
    int t = threadIdx.x;
    int tb = t % 16, tn = t / 16;
    float acc[2][5] = {{0.f}};
    for (int kc = 0; kc < 490; kc += 35) {
        for (int i = t; i < 32 * 35; i += 128) {
            int r = i / 35, c = i % 35;
            si[r][c] = g_op2[(mb + r) * 2450 + kb + kc + c];
        }
        for (int i = t; i < 40 * 35; i += 128) {
            int r = i / 35, c = i % 35;
            swt[r][c] = wf0[(nb + r) * 2450 + kb + kc + c];
        }
        __syncthreads();
#pragma unroll 5
        for (int k = 0; k < 35; k++) {
            float i0 = si[2 * tb][k], i1 = si[2 * tb + 1][k];
#pragma unroll
            for (int j = 0; j < 5; j++) {
                float wv = swt[tn * 5 + j][k];
                acc[0][j] = __fmaf_rn(i0, wv, acc[0][j]);
                acc[1][j] = __fmaf_rn(i1, wv, acc[1][j]);
            }
        }
        __syncthreads();
    }
#pragma unroll
    for (int i = 0; i < 2; i++)
#pragma unroll
        for (int j = 0; j < 5; j++)
            g_yp[(size_t)blockIdx.z * (BN * 200) + (mb + 2 * tb + i) * 200 + nb + tn * 5 + j] = acc[i][j];
}

// ---------------- fc0 fire: reduce K-split partials, membrane, Tf0 ----------------
__global__ void k_f0fire() {
    int i = blockIdx.x * blockDim.x + threadIdx.x;
    if (i >= BN * 200) return;
    float y = __fadd_rn(__fadd_rn(__fadd_rn(g_yp[i], g_yp[BN * 200 + i]),
                                  __fadd_rn(g_yp[2 * BN * 200 + i], g_yp[3 * BN * 200 + i])),
                        g_yp[4 * BN * 200 + i]);
    float m = g_mf0[i] + y;
    float o = (m > 1.f) ? 1.f : 0.f;
    g_mf0[i] = (m > 1.f) ? 0.f : m;
    g_tf0[i] += o;
}

// ---------------- final readout: out = (Tf0 @ wf1^T) / 100 ----------------
__global__ void k_final(const float* __restrict__ wf1, float* __restrict__ out) {
    int i = blockIdx.x * blockDim.x + threadIdx.x;
    if (i >= BN * 10) return;
    int b = i / 10, j = i % 10;
    const float* tf = &g_tf0[b * 200];
    const float* w  = &wf1[j * 200];
    float s = 0.f;
#pragma unroll 8
    for (int n = 0; n < 200; n++) s = __fmaf_rn(tf[n], w[n], s);
    out[i] = s / 100.0f;
}

// ---------------- launch ----------------
extern "C" void kernel_launch(void* const* d_in, const int* in_sizes, int n_in,
                              void* d_out, int out_size) {
    const float* in  = (const float*)d_in[0];
    const float* w1  = (const float*)d_in[1];
    const float* w2  = (const float*)d_in[2];
    const float* wf0 = (const float*)d_in[3];
    const float* wf1 = (const float*)d_in[4];
    float* out = (float*)d_out;

    cudaFuncSetAttribute(k_conv2, cudaFuncAttributeMaxDynamicSharedMemorySize, C2_SMEM);

    // Zero persistent state (graph-capturable async memsets)
    void* p;
    cudaGetSymbolAddress(&p, g_m1);  cudaMemsetAsync(p, 0, sizeof(float) * BN * 20 * 784);
    cudaGetSymbolAddress(&p, g_m1s); cudaMemsetAsync(p, 0, sizeof(float) * BN * 20 * 196);
    cudaGetSymbolAddress(&p, g_m2);  cudaMemsetAsync(p, 0, sizeof(float) * BN * 50 * 196);
    cudaGetSymbolAddress(&p, g_m2s); cudaMemsetAsync(p, 0, sizeof(float) * BN * 50 * 49);
    cudaGetSymbolAddress(&p, g_mf0); cudaMemsetAsync(p, 0, sizeof(float) * BN * 200);
    cudaGetSymbolAddress(&p, g_tf0); cudaMemsetAsync(p, 0, sizeof(float) * BN * 200);

    // Per-step keys: JAX partitionable split — key_t = threefry((0,42), (0,t))
    uint32_t keys[NSTEPS][2];
    for (int t = 0; t < NSTEPS; t++)
        tf2x32(0u, 42u, 0u, (uint32_t)t, keys[t][0], keys[t][1]);

    for (int t = 0; t < NSTEPS; t++) {
        k_conv1<<<dim3(BN, 4), 224>>>(in, w1, keys[t][0], keys[t][1]);
        k_conv2<<<dim3(BN, 2), 256, C2_SMEM>>>(w2);
        k_fc0  <<<dim3(16, 5, 5), 128>>>(wf0);
        k_f0fire<<<(BN * 200 + 255) / 256, 256>>>();
    }
    k_final<<<(BN * 10 + 255) / 256, 256>>>(wf1, out);
}

// round 8
// speedup vs baseline: 1.7138x; 1.7138x over previous
#include <cuda_runtime.h>
#include <cstdint>

#define BN 512
#define NSTEPS 100

// ---------------- persistent device state (allocation-free scratch) ----------------
__device__ float    g_m1 [BN * 20 * 784];  // conv1 membrane
__device__ float    g_m1s[BN * 20 * 196];  // pool1 membrane
__device__ uint32_t g_opm[BN * 196];       // pool1 output spike masks (bit ci)
__device__ float    g_m2 [BN * 50 * 196];  // conv2 membrane
__device__ float    g_m2s[BN * 50 * 49];   // pool2 membrane
__device__ float    g_op2[BN * 2450];      // pool2 output spikes, layout (b, co*49+q)
__device__ float    g_mf0[BN * 200];       // fc0 membrane
__device__ float    g_tf0[BN * 200];       // fc0 total spike count (ONLY output that matters)
__device__ float    g_yp [5 * BN * 200];   // fc0 K-split partials (order proven output-neutral)

// ---------------- Threefry-2x32, 20 rounds (matches JAX exactly) ----------------
__host__ __device__ __forceinline__ void tf2x32(uint32_t k0, uint32_t k1,
                                                uint32_t x0, uint32_t x1,
                                                uint32_t& o0, uint32_t& o1) {
    uint32_t k2 = k0 ^ k1 ^ 0x1BD11BDAu;
    x0 += k0; x1 += k1;
#define TFR(r) { x0 += x1; x1 = (x1 << (r)) | (x1 >> (32 - (r))); x1 ^= x0; }
    TFR(13) TFR(15) TFR(26) TFR(6)   x0 += k1; x1 += k2 + 1u;
    TFR(17) TFR(29) TFR(16) TFR(24)  x0 += k2; x1 += k0 + 2u;
    TFR(13) TFR(15) TFR(26) TFR(6)   x0 += k0; x1 += k1 + 3u;
    TFR(17) TFR(29) TFR(16) TFR(24)  x0 += k1; x1 += k2 + 4u;
    TFR(13) TFR(15) TFR(26) TFR(6)   x0 += k2; x1 += k0 + 5u;
#undef TFR
    o0 = x0; o1 = x1;
}

// ---------------- conv1 (RNG fused) + fire(1.0) + avgpool2 + fire(0.75) ----------------
// Round-5 form (1 block/image, RNG once). Output = 20-bit fire mask per pooled position.
__global__ __launch_bounds__(224) void k_conv1(const float* __restrict__ in,
                                               const float* __restrict__ w1,
                                               uint32_t k0, uint32_t k1) {
    int b = blockIdx.x;
    __shared__ float sin_[32][32];   // padded 28x28 (+2 halo)
    __shared__ float sw[500];        // 20 x 25 weights
    int t = threadIdx.x;
    for (int i = t; i < 1024; i += blockDim.x) ((float*)sin_)[i] = 0.f;
    for (int i = t; i < 500;  i += blockDim.x) sw[i] = w1[i];
    __syncthreads();
    for (int i = t; i < 784; i += blockDim.x) {
        uint32_t o0, o1;
        tf2x32(k0, k1, 0u, (uint32_t)(b * 784 + i), o0, o1);
        uint32_t bits = o0 ^ o1;
        float u = __uint_as_float((bits >> 9) | 0x3f800000u) - 1.0f;
        float v = in[b * 784 + i];
        float sgn = (v > 0.f) ? 1.f : ((v < 0.f) ? -1.f : 0.f);
        sin_[2 + i / 28][2 + i % 28] = (fabsf(v) * 0.5f > u) ? sgn : 0.f;
    }
    __syncthreads();

    if (t < 196) {
        int py = t / 14, px = t % 14;
        int r0 = 2 * py, c0 = 2 * px;
        float p[6][6];
#pragma unroll
        for (int r = 0; r < 6; r++)
#pragma unroll
            for (int c = 0; c < 6; c++) p[r][c] = sin_[r0 + r][c0 + c];

        uint32_t mask = 0u;
        for (int ch = 0; ch < 20; ch++) {
            const float* w = &sw[ch * 25];
            float a00 = 0.f, a01 = 0.f, a10 = 0.f, a11 = 0.f;
#pragma unroll
            for (int ky = 0; ky < 5; ky++)
#pragma unroll
                for (int kx = 0; kx < 5; kx++) {
                    float wv = w[ky * 5 + kx];
                    a00 = __fmaf_rn(p[ky][kx],         wv, a00);
                    a01 = __fmaf_rn(p[ky][kx + 1],     wv, a01);
                    a10 = __fmaf_rn(p[ky + 1][kx],     wv, a10);
                    a11 = __fmaf_rn(p[ky + 1][kx + 1], wv, a11);
                }
            size_t mb = (size_t)(b * 20 + ch) * 784;
            int i00 = r0 * 28 + c0;
            float m00 = g_m1[mb + i00]      + a00;
            float m01 = g_m1[mb + i00 + 1]  + a01;
            float m10 = g_m1[mb + i00 + 28] + a10;
            float m11 = g_m1[mb + i00 + 29] + a11;
            float f00 = (m00 > 1.f) ? 1.f : 0.f; g_m1[mb + i00]      = (m00 > 1.f) ? 0.f : m00;
            float f01 = (m01 > 1.f) ? 1.f : 0.f; g_m1[mb + i00 + 1]  = (m01 > 1.f) ? 0.f : m01;
            float f10 = (m10 > 1.f) ? 1.f : 0.f; g_m1[mb + i00 + 28] = (m10 > 1.f) ? 0.f : m10;
            float f11 = (m11 > 1.f) ? 1.f : 0.f; g_m1[mb + i00 + 29] = (m11 > 1.f) ? 0.f : m11;
            int pi = (b * 20 + ch) * 196 + t;
            float ms = g_m1s[pi] + 0.25f * (f00 + f01 + f10 + f11);
            if (ms > 0.75f) { mask |= (1u << ch); g_m1s[pi] = 0.f; }
            else            { g_m1s[pi] = ms; }
        }
        g_opm[b * 196 + t] = mask;
    }
}

// ---------------- conv2 SPARSE: sum weights at set spike bits, (ky,kx,ci) ascending ----------------
// fma(1,w,acc)==fadd(acc,w) and fma(0,w,acc)==acc exactly -> bit-identical to dense chain.
// grid (b, 2): 25 output channels per block. 256 threads = 5 cogs x 49 positions, 5 ch/thread.
#define C2_SMEM (328 * 4 + 13000 * 4)
__global__ __launch_bounds__(256) void k_conv2(const float* __restrict__ w2) {
    extern __shared__ unsigned char dynv[];
    uint32_t* sm  = (uint32_t*)dynv;              // 18x18 spike masks (halo zero)
    float*    swt = (float*)(dynv + 328 * 4);     // [kk][ci][ch], slot 26: (kk*20+ci)*26+ch
    int b  = blockIdx.x;
    int cb = blockIdx.y * 25;
    int t = threadIdx.x;
    for (int i = t; i < 324; i += 256) sm[i] = 0u;
    for (int i = t; i < 12500; i += 256) {
        int ch = i / 500, rem = i % 500, kk = rem / 20, ci = rem % 20;
        swt[(kk * 20 + ci) * 26 + ch] = w2[(cb + ch) * 500 + ci * 25 + kk];
    }
    __syncthreads();
    for (int i = t; i < 196; i += 256) {
        int rr = i / 14, cc = i % 14;
        sm[(rr + 2) * 18 + (cc + 2)] = g_opm[b * 196 + i];
    }
    __syncthreads();

    if (t < 245) {
        int cog = t / 49, q = t % 49;
        int py = q / 7, px = q % 7;
        int r0 = 2 * py, c0 = 2 * px;
        float acc[5][4] = {};
#pragma unroll 1
        for (int ky = 0; ky < 5; ky++) {
            const uint32_t* mr0 = &sm[(r0 + ky) * 18 + c0];
            const uint32_t* mr1 = mr0 + 18;
#pragma unroll 1
            for (int kx = 0; kx < 5; kx++) {
                uint32_t m0 = mr0[kx], m1 = mr0[kx + 1];
                uint32_t m2 = mr1[kx], m3 = mr1[kx + 1];
                const float* wk = &swt[(ky * 5 + kx) * 20 * 26 + cog * 5];
                while (m0) {
                    int ci = __ffs(m0) - 1; m0 &= m0 - 1;
                    const float* w = wk + ci * 26;
                    acc[0][0] = __fadd_rn(acc[0][0], w[0]);
                    acc[1][0] = __fadd_rn(acc[1][0], w[1]);
                    acc[2][0] = __fadd_rn(acc[2][0], w[2]);
                    acc[3][0] = __fadd_rn(acc[3][0], w[3]);
                    acc[4][0] = __fadd_rn(acc[4][0], w[4]);
                }
                while (m1) {
                    int ci = __ffs(m1) - 1; m1 &= m1 - 1;
                    const float* w = wk + ci * 26;
                    acc[0][1] = __fadd_rn(acc[0][1], w[0]);
                    acc[1][1] = __fadd_rn(acc[1][1], w[1]);
                    acc[2][1] = __fadd_rn(acc[2][1], w[2]);
                    acc[3][1] = __fadd_rn(acc[3][1], w[3]);
                    acc[4][1] = __fadd_rn(acc[4][1], w[4]);
                }
                while (m2) {
                    int ci = __ffs(m2) - 1; m2 &= m2 - 1;
                    const float* w = wk + ci * 26;
                    acc[0][2] = __fadd_rn(acc[0][2], w[0]);
                    acc[1][2] = __fadd_rn(acc[1][2], w[1]);
                    acc[2][2] = __fadd_rn(acc[2][2], w[2]);
                    acc[3][2] = __fadd_rn(acc[3][2], w[3]);
                    acc[4][2] = __fadd_rn(acc[4][2], w[4]);
                }
                while (m3) {
                    int ci = __ffs(m3) - 1; m3 &= m3 - 1;
                    const float* w = wk + ci * 26;
                    acc[0][3] = __fadd_rn(acc[0][3], w[0]);
                    acc[1][3] = __fadd_rn(acc[1][3], w[1]);
                    acc[2][3] = __fadd_rn(acc[2][3], w[2]);
                    acc[3][3] = __fadd_rn(acc[3][3], w[3]);
                    acc[4][3] = __fadd_rn(acc[4][3], w[4]);
                }
            }
        }
#pragma unroll
        for (int u = 0; u < 5; u++) {
            int co = cb + cog * 5 + u;
            size_t mb = (size_t)(b * 50 + co) * 196;
            int i00 = r0 * 14 + c0;
            float m00 = g_m2[mb + i00]      + acc[u][0];
            float m01 = g_m2[mb + i00 + 1]  + acc[u][1];
            float m10 = g_m2[mb + i00 + 14] + acc[u][2];
            float m11 = g_m2[mb + i00 + 15] + acc[u][3];
            float f00 = (m00 > 1.f) ? 1.f : 0.f; g_m2[mb + i00]      = (m00 > 1.f) ? 0.f : m00;
            float f01 = (m01 > 1.f) ? 1.f : 0.f; g_m2[mb + i00 + 1]  = (m01 > 1.f) ? 0.f : m01;
            float f10 = (m10 > 1.f) ? 1.f : 0.f; g_m2[mb + i00 + 14] = (m10 > 1.f) ? 0.f : m10;
            float f11 = (m11 > 1.f) ? 1.f : 0.f; g_m2[mb + i00 + 15] = (m11 > 1.f) ? 0.f : m11;
            int pi = (b * 50 + co) * 49 + q;
            float ms = g_m2s[pi] + 0.25f * (f00 + f01 + f10 + f11);
            float op = (ms > 0.75f) ? 1.f : 0.f;
            g_m2s[pi] = (ms > 0.75f) ? 0.f : ms;
            g_op2[b * 2450 + co * 49 + q] = op;
        }
    }
}

// ---------------- fc0 GEMM split-K x5 (proven output-neutral), scalar (round-5 exact) ----------------
__global__ __launch_bounds__(128) void k_fc0(const float* __restrict__ wf0) {
    int mb = blockIdx.x * 32;
    int nb = blockIdx.y * 40;
    int kb = blockIdx.z * 490;
    __shared__ float si[32][36];
    __shared__ float swt[40][36];
    int t = threadIdx.x;
    int tb = t % 16, tn = t / 16;
    float acc[2][5] = {{0.f}};
    for (int kc = 0; kc < 490; kc += 35) {
        for (int i = t; i < 32 * 35; i += 128) {
            int r = i / 35, c = i % 35;
            si[r][c] = g_op2[(mb + r) * 2450 + kb + kc + c];
        }
        for (int i = t; i < 40 * 35; i += 128) {
            int r = i / 35, c = i % 35;
            swt[r][c] = wf0[(nb + r) * 2450 + kb + kc + c];
        }
        __syncthreads();
#pragma unroll 5
        for (int k = 0; k < 35; k++) {
            float i0 = si[2 * tb][k], i1 = si[2 * tb + 1][k];
#pragma unroll
            for (int j = 0; j < 5; j++) {
                float wv = swt[tn * 5 + j][k];
                acc[0][j] = __fmaf_rn(i0, wv, acc[0][j]);
                acc[1][j] = __fmaf_rn(i1, wv, acc[1][j]);
            }
        }
        __syncthreads();
    }
#pragma unroll
    for (int i = 0; i < 2; i++)
#pragma unroll
        for (int j = 0; j < 5; j++)
            g_yp[(size_t)blockIdx.z * (BN * 200) + (mb + 2 * tb + i) * 200 + nb + tn * 5 + j] = acc[i][j];
}

// ---------------- fc0 fire: reduce K-split partials, membrane, Tf0 ----------------
__global__ void k_f0fire() {
    int i = blockIdx.x * blockDim.x + threadIdx.x;
    if (i >= BN * 200) return;
    float y = __fadd_rn(__fadd_rn(__fadd_rn(g_yp[i], g_yp[BN * 200 + i]),
                                  __fadd_rn(g_yp[2 * BN * 200 + i], g_yp[3 * BN * 200 + i])),
                        g_yp[4 * BN * 200 + i]);
    float m = g_mf0[i] + y;
    float o = (m > 1.f) ? 1.f : 0.f;
    g_mf0[i] = (m > 1.f) ? 0.f : m;
    g_tf0[i] += o;
}

// ---------------- final readout: out = (Tf0 @ wf1^T) / 100 ----------------
__global__ void k_final(const float* __restrict__ wf1, float* __restrict__ out) {
    int i = blockIdx.x * blockDim.x + threadIdx.x;
    if (i >= BN * 10) return;
    int b = i / 10, j = i % 10;
    const float* tf = &g_tf0[b * 200];
    const float* w  = &wf1[j * 200];
    float s = 0.f;
#pragma unroll 8
    for (int n = 0; n < 200; n++) s = __fmaf_rn(tf[n], w[n], s);
    out[i] = s / 100.0f;
}

// ---------------- launch ----------------
extern "C" void kernel_launch(void* const* d_in, const int* in_sizes, int n_in,
                              void* d_out, int out_size) {
    const float* in  = (const float*)d_in[0];
    const float* w1  = (const float*)d_in[1];
    const float* w2  = (const float*)d_in[2];
    const float* wf0 = (const float*)d_in[3];
    const float* wf1 = (const float*)d_in[4];
    float* out = (float*)d_out;

    cudaFuncSetAttribute(k_conv2, cudaFuncAttributeMaxDynamicSharedMemorySize, C2_SMEM);

    // Zero persistent state (graph-capturable async memsets)
    void* p;
    cudaGetSymbolAddress(&p, g_m1);  cudaMemsetAsync(p, 0, sizeof(float) * BN * 20 * 784);
    cudaGetSymbolAddress(&p, g_m1s); cudaMemsetAsync(p, 0, sizeof(float) * BN * 20 * 196);
    cudaGetSymbolAddress(&p, g_m2);  cudaMemsetAsync(p, 0, sizeof(float) * BN * 50 * 196);
    cudaGetSymbolAddress(&p, g_m2s); cudaMemsetAsync(p, 0, sizeof(float) * BN * 50 * 49);
    cudaGetSymbolAddress(&p, g_mf0); cudaMemsetAsync(p, 0, sizeof(float) * BN * 200);
    cudaGetSymbolAddress(&p, g_tf0); cudaMemsetAsync(p, 0, sizeof(float) * BN * 200);

    // Per-step keys: JAX partitionable split — key_t = threefry((0,42), (0,t))
    uint32_t keys[NSTEPS][2];
    for (int t = 0; t < NSTEPS; t++)
        tf2x32(0u, 42u, 0u, (uint32_t)t, keys[t][0], keys[t][1]);

    for (int t = 0; t < NSTEPS; t++) {
        k_conv1<<<BN, 224>>>(in, w1, keys[t][0], keys[t][1]);
        k_conv2<<<dim3(BN, 2), 256, C2_SMEM>>>(w2);
        k_fc0  <<<dim3(16, 5, 5), 128>>>(wf0);
        k_f0fire<<<(BN * 200 + 255) / 256, 256>>>();
    }
    k_final<<<(BN * 10 + 255) / 256, 256>>>(wf1, out);
}

// round 10
// speedup vs baseline: 2.7368x; 1.5969x over previous
#include <cuda_runtime.h>
#include <cstdint>

#define BN 512
#define NSTEPS 100

// ---------------- persistent device state (allocation-free scratch) ----------------
__device__ float    g_m1 [BN * 20 * 784];  // conv1 membrane
__device__ float    g_m1s[BN * 20 * 196];  // pool1 membrane
__device__ uint32_t g_opm[BN * 196];       // pool1 output spike masks (bit ci)
__device__ float    g_m2 [BN * 50 * 196];  // conv2 membrane
__device__ float    g_m2s[BN * 50 * 49];   // pool2 membrane
__device__ uint32_t g_op2m[BN][2][40];     // pool2 spike masks: region cb, 39 words (k=cb*1225+w*32+j)
__device__ float    g_mf0[BN * 200];       // fc0 membrane
__device__ float    g_tf0[BN * 200];       // fc0 total spike count (ONLY output that matters)
__device__ float    g_w2t [2 * 500 * 26];  // conv2 weights pre-transposed [cb][kk*20+ci][ch pad26]
__device__ float    g_wf0T[2450 * 200];    // wf0 transposed [k][n]

// ---------------- Threefry-2x32, 20 rounds (matches JAX exactly) ----------------
__host__ __device__ __forceinline__ void tf2x32(uint32_t k0, uint32_t k1,
                                                uint32_t x0, uint32_t x1,
                                                uint32_t& o0, uint32_t& o1) {
    uint32_t k2 = k0 ^ k1 ^ 0x1BD11BDAu;
    x0 += k0; x1 += k1;
#define TFR(r) { x0 += x1; x1 = (x1 << (r)) | (x1 >> (32 - (r))); x1 ^= x0; }
    TFR(13) TFR(15) TFR(26) TFR(6)   x0 += k1; x1 += k2 + 1u;
    TFR(17) TFR(29) TFR(16) TFR(24)  x0 += k2; x1 += k0 + 2u;
    TFR(13) TFR(15) TFR(26) TFR(6)   x0 += k0; x1 += k1 + 3u;
    TFR(17) TFR(29) TFR(16) TFR(24)  x0 += k1; x1 += k2 + 4u;
    TFR(13) TFR(15) TFR(26) TFR(6)   x0 += k2; x1 += k0 + 5u;
#undef TFR
    o0 = x0; o1 = x1;
}

// ---------------- one-time prep: transpose w2 and wf0 (runs once per launch, in-graph) ----------------
__global__ void k_prep(const float* __restrict__ w2, const float* __restrict__ wf0) {
    int i = blockIdx.x * blockDim.x + threadIdx.x;
    // g_w2t[(cb*500 + kk*20+ci)*26 + ch] = w2[(cb*25+ch)*500 + ci*25 + kk]
    if (i < 2 * 500 * 26) {
        int ch = i % 26, rem = i / 26, kkci = rem % 500, cb = rem / 500;
        int kk = kkci / 20, ci = kkci % 20;
        g_w2t[i] = (ch < 25) ? w2[(cb * 25 + ch) * 500 + ci * 25 + kk] : 0.f;
    }
    // g_wf0T[k*200+n] = wf0[n*2450+k]
    int j = i - 2 * 500 * 26;
    if (j >= 0 && j < 2450 * 200) {
        int n = j % 200, k = j / 200;
        g_wf0T[j] = wf0[n * 2450 + k];
    }
}

// ---------------- conv1 (RNG fused) + fire(1.0) + avgpool2 + fire(0.75) ----------------
__global__ __launch_bounds__(224) void k_conv1(const float* __restrict__ in,
                                               const float* __restrict__ w1,
                                               uint32_t k0, uint32_t k1) {
    int b = blockIdx.x;
    __shared__ float sin_[32][32];   // padded 28x28 (+2 halo)
    __shared__ float sw[500];        // 20 x 25 weights
    int t = threadIdx.x;
    for (int i = t; i < 1024; i += blockDim.x) ((float*)sin_)[i] = 0.f;
    for (int i = t; i < 500;  i += blockDim.x) sw[i] = w1[i];
    __syncthreads();
    for (int i = t; i < 784; i += blockDim.x) {
        uint32_t o0, o1;
        tf2x32(k0, k1, 0u, (uint32_t)(b * 784 + i), o0, o1);
        uint32_t bits = o0 ^ o1;
        float u = __uint_as_float((bits >> 9) | 0x3f800000u) - 1.0f;
        float v = in[b * 784 + i];
        float sgn = (v > 0.f) ? 1.f : ((v < 0.f) ? -1.f : 0.f);
        sin_[2 + i / 28][2 + i % 28] = (fabsf(v) * 0.5f > u) ? sgn : 0.f;
    }
    __syncthreads();

    if (t < 196) {
        int py = t / 14, px = t % 14;
        int r0 = 2 * py, c0 = 2 * px;
        float p[6][6];
#pragma unroll
        for (int r = 0; r < 6; r++)
#pragma unroll
            for (int c = 0; c < 6; c++) p[r][c] = sin_[r0 + r][c0 + c];

        uint32_t mask = 0u;
        for (int ch = 0; ch < 20; ch++) {
            const float* w = &sw[ch * 25];
            float a00 = 0.f, a01 = 0.f, a10 = 0.f, a11 = 0.f;
#pragma unroll
            for (int ky = 0; ky < 5; ky++)
#pragma unroll
                for (int kx = 0; kx < 5; kx++) {
                    float wv = w[ky * 5 + kx];
                    a00 = __fmaf_rn(p[ky][kx],         wv, a00);
                    a01 = __fmaf_rn(p[ky][kx + 1],     wv, a01);
                    a10 = __fmaf_rn(p[ky + 1][kx],     wv, a10);
                    a11 = __fmaf_rn(p[ky + 1][kx + 1], wv, a11);
                }
            size_t mb = (size_t)(b * 20 + ch) * 784;
            int i00 = r0 * 28 + c0;
            float m00 = g_m1[mb + i00]      + a00;
            float m01 = g_m1[mb + i00 + 1]  + a01;
            float m10 = g_m1[mb + i00 + 28] + a10;
            float m11 = g_m1[mb + i00 + 29] + a11;
            float f00 = (m00 > 1.f) ? 1.f : 0.f; g_m1[mb + i00]      = (m00 > 1.f) ? 0.f : m00;
            float f01 = (m01 > 1.f) ? 1.f : 0.f; g_m1[mb + i00 + 1]  = (m01 > 1.f) ? 0.f : m01;
            float f10 = (m10 > 1.f) ? 1.f : 0.f; g_m1[mb + i00 + 28] = (m10 > 1.f) ? 0.f : m10;
            float f11 = (m11 > 1.f) ? 1.f : 0.f; g_m1[mb + i00 + 29] = (m11 > 1.f) ? 0.f : m11;
            int pi = (b * 20 + ch) * 196 + t;
            float ms = g_m1s[pi] + 0.25f * (f00 + f01 + f10 + f11);
            if (ms > 0.75f) { mask |= (1u << ch); g_m1s[pi] = 0.f; }
            else            { g_m1s[pi] = ms; }
        }
        g_opm[b * 196 + t] = mask;
    }
}

// ---------------- conv2 SPARSE, 2 images/block; emits pool2 bit-masks ----------------
// grid (BN/2, 2). 256 threads = 5 cogs x 49 positions, 5 ch/thread. Inner chain = round-8 exact.
#define C2_SMEM ((364 + 13000) * 4)
__global__ __launch_bounds__(256) void k_conv2() {
    extern __shared__ unsigned char dynv[];
    uint32_t* sm    = (uint32_t*)dynv;               // 18x18 spike masks (halo zero)
    uint32_t* smask = (uint32_t*)dynv + 324;         // 40-word output mask
    float*    swt   = (float*)(dynv + 364 * 4);      // [kk][ci][ch] slot 26
    int b0 = blockIdx.x * 2;
    int cb = blockIdx.y;
    int t = threadIdx.x;
    // stage weights once: pure float4 copy from pre-transposed global
    {
        const float4* src = (const float4*)(g_w2t + cb * 13000);
        float4* dst = (float4*)swt;
        for (int i = t; i < 3250; i += 256) dst[i] = src[i];
    }

    for (int bi = 0; bi < 2; bi++) {
        int b = b0 + bi;
        __syncthreads();   // smem reuse barrier (covers staged weights on bi=0, prior readout on bi=1)
        for (int i = t; i < 324; i += 256) {
            int rr = i / 18 - 2, cc = i % 18 - 2;
            sm[i] = (rr >= 0 && rr < 14 && cc >= 0 && cc < 14) ? g_opm[b * 196 + rr * 14 + cc] : 0u;
        }
        if (t < 40) smask[t] = 0u;   // FIX: was guarded by t>=324 (dead with 256 threads)
        __syncthreads();

        if (t < 245) {
            int cog = t / 49, q = t % 49;
            int py = q / 7, px = q % 7;
            int r0 = 2 * py, c0 = 2 * px;
            float acc[5][4] = {};
#pragma unroll 1
            for (int ky = 0; ky < 5; ky++) {
                const uint32_t* mr0 = &sm[(r0 + ky) * 18 + c0];
                const uint32_t* mr1 = mr0 + 18;
#pragma unroll 1
                for (int kx = 0; kx < 5; kx++) {
                    uint32_t m0 = mr0[kx], m1 = mr0[kx + 1];
                    uint32_t m2 = mr1[kx], m3 = mr1[kx + 1];
                    const float* wk = &swt[(ky * 5 + kx) * 20 * 26 + cog * 5];
                    while (m0) {
                        int ci = __ffs(m0) - 1; m0 &= m0 - 1;
                        const float* w = wk + ci * 26;
                        acc[0][0] = __fadd_rn(acc[0][0], w[0]);
                        acc[1][0] = __fadd_rn(acc[1][0], w[1]);
                        acc[2][0] = __fadd_rn(acc[2][0], w[2]);
                        acc[3][0] = __fadd_rn(acc[3][0], w[3]);
                        acc[4][0] = __fadd_rn(acc[4][0], w[4]);
                    }
                    while (m1) {
                        int ci = __ffs(m1) - 1; m1 &= m1 - 1;
                        const float* w = wk + ci * 26;
                        acc[0][1] = __fadd_rn(acc[0][1], w[0]);
                        acc[1][1] = __fadd_rn(acc[1][1], w[1]);
                        acc[2][1] = __fadd_rn(acc[2][1], w[2]);
                        acc[3][1] = __fadd_rn(acc[3][1], w[3]);
                        acc[4][1] = __fadd_rn(acc[4][1], w[4]);
                    }
                    while (m2) {
                        int ci = __ffs(m2) - 1; m2 &= m2 - 1;
                        const float* w = wk + ci * 26;
                        acc[0][2] = __fadd_rn(acc[0][2], w[0]);
                        acc[1][2] = __fadd_rn(acc[1][2], w[1]);
                        acc[2][2] = __fadd_rn(acc[2][2], w[2]);
                        acc[3][2] = __fadd_rn(acc[3][2], w[3]);
                        acc[4][2] = __fadd_rn(acc[4][2], w[4]);
                    }
                    while (m3) {
                        int ci = __ffs(m3) - 1; m3 &= m3 - 1;
                        const float* w = wk + ci * 26;
                        acc[0][3] = __fadd_rn(acc[0][3], w[0]);
                        acc[1][3] = __fadd_rn(acc[1][3], w[1]);
                        acc[2][3] = __fadd_rn(acc[2][3], w[2]);
                        acc[3][3] = __fadd_rn(acc[3][3], w[3]);
                        acc[4][3] = __fadd_rn(acc[4][3], w[4]);
                    }
                }
            }
#pragma unroll
            for (int u = 0; u < 5; u++) {
                int colocal = cog * 5 + u;
                int co = cb * 25 + colocal;
                size_t mb = (size_t)(b * 50 + co) * 196;
                int i00 = r0 * 14 + c0;
                float m00 = g_m2[mb + i00]      + acc[u][0];
                float m01 = g_m2[mb + i00 + 1]  + acc[u][1];
                float m10 = g_m2[mb + i00 + 14] + acc[u][2];
                float m11 = g_m2[mb + i00 + 15] + acc[u][3];
                float f00 = (m00 > 1.f) ? 1.f : 0.f; g_m2[mb + i00]      = (m00 > 1.f) ? 0.f : m00;
                float f01 = (m01 > 1.f) ? 1.f : 0.f; g_m2[mb + i00 + 1]  = (m01 > 1.f) ? 0.f : m01;
                float f10 = (m10 > 1.f) ? 1.f : 0.f; g_m2[mb + i00 + 14] = (m10 > 1.f) ? 0.f : m10;
                float f11 = (m11 > 1.f) ? 1.f : 0.f; g_m2[mb + i00 + 15] = (m11 > 1.f) ? 0.f : m11;
                int pi = (b * 50 + co) * 49 + q;
                float ms = g_m2s[pi] + 0.25f * (f00 + f01 + f10 + f11);
                if (ms > 0.75f) {
                    g_m2s[pi] = 0.f;
                    int bit = colocal * 49 + q;
                    atomicOr(&smask[bit >> 5], 1u << (bit & 31));
                } else {
                    g_m2s[pi] = ms;
                }
            }
        }
        __syncthreads();
        if (t < 39) g_op2m[b][cb][t] = smask[t];
    }
}

// ---------------- fc0 SPARSE: acc = sum of wf0T[k][n] over set k ascending; fire fused ----------------
// Single ascending-k chain (proven bit-identical to split-K in rounds 1/3/4/5).
__global__ __launch_bounds__(256) void k_fc0s() {
    int b = blockIdx.x;
    __shared__ uint32_t mw[78];
    __shared__ int pfx[79];
    __shared__ uint16_t klist[2450];
    int t = threadIdx.x;
    if (t < 39)            mw[t] = g_op2m[b][0][t];
    else if (t < 78)       mw[t] = g_op2m[b][1][t - 39];
    __syncthreads();
    if (t == 0) {
        int s = 0;
        for (int w = 0; w < 78; w++) { pfx[w] = s; s += __popc(mw[w]); }
        pfx[78] = s;
    }
    __syncthreads();
    if (t < 78) {
        uint32_t m = mw[t];
        int base = (t < 39 ? 0 : 1225) + (t < 39 ? t : t - 39) * 32;
        int o = pfx[t];
        while (m) { int j = __ffs(m) - 1; m &= m - 1; klist[o++] = (uint16_t)(base + j); }
    }
    __syncthreads();
    int nb = pfx[78];
    if (t < 200) {
        const float* col = g_wf0T + t;
        float acc = 0.f;
        int i = 0;
        for (; i + 8 <= nb; i += 8) {
            float v0 = __ldg(&col[(int)klist[i]     * 200]);
            float v1 = __ldg(&col[(int)klist[i + 1] * 200]);
            float v2 = __ldg(&col[(int)klist[i + 2] * 200]);
            float v3 = __ldg(&col[(int)klist[i + 3] * 200]);
            float v4 = __ldg(&col[(int)klist[i + 4] * 200]);
            float v5 = __ldg(&col[(int)klist[i + 5] * 200]);
            float v6 = __ldg(&col[(int)klist[i + 6] * 200]);
            float v7 = __ldg(&col[(int)klist[i + 7] * 200]);
            acc = __fadd_rn(acc, v0); acc = __fadd_rn(acc, v1);
            acc = __fadd_rn(acc, v2); acc = __fadd_rn(acc, v3);
            acc = __fadd_rn(acc, v4); acc = __fadd_rn(acc, v5);
            acc = __fadd_rn(acc, v6); acc = __fadd_rn(acc, v7);
        }
        for (; i < nb; i++) acc = __fadd_rn(acc, __ldg(&col[(int)klist[i] * 200]));
        int idx = b * 200 + t;
        float m = g_mf0[idx] + acc;
        float o = (m > 1.f) ? 1.f : 0.f;
        g_mf0[idx] = (m > 1.f) ? 0.f : m;
        g_tf0[idx] += o;
    }
}

// ---------------- final readout: out = (Tf0 @ wf1^T) / 100 ----------------
__global__ void k_final(const float* __restrict__ wf1, float* __restrict__ out) {
    int i = blockIdx.x * blockDim.x + threadIdx.x;
    if (i >= BN * 10) return;
    int b = i / 10, j = i % 10;
    const float* tf = &g_tf0[b * 200];
    const float* w  = &wf1[j * 200];
    float s = 0.f;
#pragma unroll 8
    for (int n = 0; n < 200; n++) s = __fmaf_rn(tf[n], w[n], s);
    out[i] = s / 100.0f;
}

// ---------------- launch ----------------
extern "C" void kernel_launch(void* const* d_in, const int* in_sizes, int n_in,
                              void* d_out, int out_size) {
    const float* in  = (const float*)d_in[0];
    const float* w1  = (const float*)d_in[1];
    const float* w2  = (const float*)d_in[2];
    const float* wf0 = (const float*)d_in[3];
    const float* wf1 = (const float*)d_in[4];
    float* out = (float*)d_out;

    cudaFuncSetAttribute(k_conv2, cudaFuncAttributeMaxDynamicSharedMemorySize, C2_SMEM);

    // Zero persistent state (graph-capturable async memsets)
    void* p;
    cudaGetSymbolAddress(&p, g_m1);  cudaMemsetAsync(p, 0, sizeof(float) * BN * 20 * 784);
    cudaGetSymbolAddress(&p, g_m1s); cudaMemsetAsync(p, 0, sizeof(float) * BN * 20 * 196);
    cudaGetSymbolAddress(&p, g_m2);  cudaMemsetAsync(p, 0, sizeof(float) * BN * 50 * 196);
    cudaGetSymbolAddress(&p, g_m2s); cudaMemsetAsync(p, 0, sizeof(float) * BN * 50 * 49);
    cudaGetSymbolAddress(&p, g_mf0); cudaMemsetAsync(p, 0, sizeof(float) * BN * 200);
    cudaGetSymbolAddress(&p, g_tf0); cudaMemsetAsync(p, 0, sizeof(float) * BN * 200);

    // One-time transposes (in-graph, before the step loop)
    k_prep<<<(2 * 500 * 26 + 2450 * 200 + 255) / 256, 256>>>(w2, wf0);

    // Per-step keys: JAX partitionable split — key_t = threefry((0,42), (0,t))
    uint32_t keys[NSTEPS][2];
    for (int t = 0; t < NSTEPS; t++)
        tf2x32(0u, 42u, 0u, (uint32_t)t, keys[t][0], keys[t][1]);

    for (int t = 0; t < NSTEPS; t++) {
        k_conv1<<<BN, 224>>>(in, w1, keys[t][0], keys[t][1]);
        k_conv2<<<dim3(BN / 2, 2), 256, C2_SMEM>>>();
        k_fc0s <<<BN, 256>>>();
    }
    k_final<<<(BN * 10 + 255) / 256, 256>>>(wf1, out);
}